// round 2
// baseline (speedup 1.0000x reference)
#include <cuda_runtime.h>
#include <math.h>

#define N_NODES 50000
#define N_EDGES 800000
#define DIM 128

// ---------------- scratch (static device globals; no allocation) ----------------
__device__ int   g_is64;
__device__ int   g_cnt[N_NODES];
__device__ float g_dinv[N_NODES];
__device__ int   g_offs[N_NODES + 1];
__device__ int   g_cursor[N_NODES];
__device__ int   g_src[N_EDGES];
__device__ float g_w[N_EDGES];
__device__ float g_bufA[(size_t)N_NODES * DIM];
__device__ float g_bufB[(size_t)N_NODES * DIM];
__device__ float g_Wt0[DIM * DIM];
__device__ float g_Wt1[DIM * DIM];
__device__ float g_Wt2[DIM * 64];

// ---------------- edge-index dtype detection ----------------
// int64 layout viewed as int32: [lo0, hi0, lo1, hi1, ...] with hi==0 (values < 2^31).
// int32 layout: odd words are random node ids, essentially never all zero over 1024 samples.
__global__ void detect_kernel(const int* __restrict__ w) {
    __shared__ int nz;
    if (threadIdx.x == 0) nz = 0;
    __syncthreads();
    if (w[2 * threadIdx.x + 1] != 0) atomicOr(&nz, 1);
    __syncthreads();
    if (threadIdx.x == 0) g_is64 = (nz == 0) ? 1 : 0;
}

__device__ __forceinline__ int load_idx(const void* ei, int pos) {
    return g_is64 ? (int)((const long long*)ei)[pos] : ((const int*)ei)[pos];
}

// ---------------- preprocessing kernels ----------------
__global__ void zero_cnt_kernel() {
    int i = blockIdx.x * blockDim.x + threadIdx.x;
    if (i < N_NODES) g_cnt[i] = 0;
}

__global__ void hist_kernel(const void* __restrict__ ei, int E) {
    int i = blockIdx.x * blockDim.x + threadIdx.x;
    if (i < E) {
        int c = load_idx(ei, E + i);   // col = second row of [2, E]
        if ((unsigned)c < N_NODES) atomicAdd(&g_cnt[c], 1);
    }
}

__global__ void dinv_kernel() {
    int i = blockIdx.x * blockDim.x + threadIdx.x;
    // deg includes the self-loop -> always >= 1
    if (i < N_NODES) g_dinv[i] = rsqrtf((float)(g_cnt[i] + 1));
}

// Single-block exclusive scan over g_cnt -> g_offs / g_cursor (n = 50000).
__global__ void scan_kernel(int n) {
    __shared__ int wsum[32];
    __shared__ int s_carry;
    int tid = threadIdx.x, lane = tid & 31, wid = tid >> 5;
    if (tid == 0) s_carry = 0;
    __syncthreads();
    for (int base = 0; base < n; base += 1024) {
        int i = base + tid;
        int v = (i < n) ? g_cnt[i] : 0;
        int x = v;
        #pragma unroll
        for (int d = 1; d < 32; d <<= 1) {
            int t = __shfl_up_sync(0xffffffffu, x, d);
            if (lane >= d) x += t;
        }
        if (lane == 31) wsum[wid] = x;
        __syncthreads();
        if (tid < 32) {
            int s = wsum[tid];
            #pragma unroll
            for (int d = 1; d < 32; d <<= 1) {
                int t = __shfl_up_sync(0xffffffffu, s, d);
                if (tid >= d) s += t;
            }
            wsum[tid] = s;  // inclusive scan of warp totals
        }
        __syncthreads();
        int carry = s_carry;
        int wpre = (wid == 0) ? 0 : wsum[wid - 1];
        int excl = carry + wpre + (x - v);
        if (i < n) { g_offs[i] = excl; g_cursor[i] = excl; }
        int total = wsum[31];
        __syncthreads();
        if (tid == 0) s_carry = carry + total;
        __syncthreads();
    }
    if (tid == 0) g_offs[n] = s_carry;
}

__global__ void scatter_kernel(const void* __restrict__ ei, int E) {
    int i = blockIdx.x * blockDim.x + threadIdx.x;
    if (i < E) {
        int r = load_idx(ei, i);
        int c = load_idx(ei, E + i);
        if ((unsigned)r < N_NODES && (unsigned)c < N_NODES) {
            int pos = atomicAdd(&g_cursor[c], 1);
            if ((unsigned)pos < N_EDGES) {
                g_src[pos] = r;
                g_w[pos] = g_dinv[r] * g_dinv[c];
            }
        }
    }
}

// Wt[k][n] = W[n][k]  (K = 128 fixed). wsel selects destination global.
__global__ void transpose_kernel(const float* __restrict__ W, int dout, int wsel) {
    float* Wt = (wsel == 0) ? g_Wt0 : (wsel == 1) ? g_Wt1 : g_Wt2;
    int idx = blockIdx.x * blockDim.x + threadIdx.x;
    if (idx < 128 * dout) {
        int n = idx / 128, k = idx % 128;
        Wt[k * dout + n] = W[idx];
    }
}

// ---------------- fp32 GEMM: g_bufA[N,DOUT] = X[N,128] @ Wt ([128][DOUT]) ----------------
// src_global: X = g_bufB; else X = Xext. wsel picks weight global.
template <int DOUT>
__global__ void gemm_kernel(const float* __restrict__ Xext, int src_global, int wsel,
                            int nrows) {
    constexpr int BM = 64;
    constexpr int TN = 4;
    constexpr int NCG = DOUT / TN;                 // 32 or 16 col-groups
    constexpr int TM = (BM * DOUT) / (256 * TN);   // 8 or 4 rows per thread
    const float* X = src_global ? g_bufB : Xext;
    const float* Wt = (wsel == 0) ? g_Wt0 : (wsel == 1) ? g_Wt1 : g_Wt2;
    float* Y = g_bufA;
    extern __shared__ float smem[];
    float* Xs = smem;                  // [BM][128]
    float* Ws = smem + BM * DIM;       // [128][DOUT]
    int tid = threadIdx.x;
    int row_base = blockIdx.x * BM;

    for (int idx = tid; idx < DIM * DOUT / 4; idx += 256)
        ((float4*)Ws)[idx] = ((const float4*)Wt)[idx];
    for (int idx = tid; idx < BM * DIM / 4; idx += 256) {
        int r = idx >> 5;
        int c4 = idx & 31;
        float4 v = make_float4(0.f, 0.f, 0.f, 0.f);
        int gr = row_base + r;
        if (gr < nrows) v = ((const float4*)(X + (size_t)gr * DIM))[c4];
        ((float4*)(Xs + r * DIM))[c4] = v;
    }
    __syncthreads();

    int cg = tid % NCG, rg = tid / NCG;
    int col0 = cg * TN, row0 = rg * TM;
    float acc[TM][TN];
    #pragma unroll
    for (int m = 0; m < TM; m++)
        #pragma unroll
        for (int n = 0; n < TN; n++) acc[m][n] = 0.f;

    #pragma unroll 2
    for (int k4 = 0; k4 < DIM / 4; k4++) {
        float4 av[TM];
        #pragma unroll
        for (int m = 0; m < TM; m++)
            av[m] = *(const float4*)(Xs + (row0 + m) * DIM + k4 * 4);
        #pragma unroll
        for (int kk = 0; kk < 4; kk++) {
            float4 bv = *(const float4*)(Ws + (k4 * 4 + kk) * DOUT + col0);
            #pragma unroll
            for (int m = 0; m < TM; m++) {
                float a = (kk == 0) ? av[m].x : (kk == 1) ? av[m].y : (kk == 2) ? av[m].z : av[m].w;
                acc[m][0] = fmaf(a, bv.x, acc[m][0]);
                acc[m][1] = fmaf(a, bv.y, acc[m][1]);
                acc[m][2] = fmaf(a, bv.z, acc[m][2]);
                acc[m][3] = fmaf(a, bv.w, acc[m][3]);
            }
        }
    }

    #pragma unroll
    for (int m = 0; m < TM; m++) {
        int gr = row_base + row0 + m;
        if (gr < nrows)
            *(float4*)(Y + (size_t)gr * DOUT + col0) =
                make_float4(acc[m][0], acc[m][1], acc[m][2], acc[m][3]);
    }
}

// ---------------- propagate (pull/gather via CSR) + bias (+ relu) ----------------
// Reads g_bufA; writes g_bufB (dst_ext==0) or the external pointer (dst_ext==1).
// block = one node, blockDim = DOUT; each thread owns one output feature.
template <int DOUT, bool RELU>
__global__ void prop_kernel(const float* __restrict__ bias, float* __restrict__ out_ext,
                            int dst_ext) {
    const float* Y = g_bufA;
    float* out = dst_ext ? out_ext : g_bufB;
    int node = blockIdx.x;
    int col = threadIdx.x;
    float di = g_dinv[node];
    float acc = di * di * Y[node * DOUT + col];   // self-loop term
    int e = g_offs[node];
    int end = g_offs[node + 1];
    #pragma unroll 4
    for (; e < end; e++) {
        int s = g_src[e];
        acc = fmaf(g_w[e], Y[s * DOUT + col], acc);
    }
    acc += bias[col];
    if (RELU) acc = fmaxf(acc, 0.f);
    out[node * DOUT + col] = acc;
}

// ---------------- host entry ----------------
extern "C" void kernel_launch(void* const* d_in, const int* in_sizes, int n_in,
                              void* d_out, int out_size) {
    const float* x  = (const float*)d_in[0];
    const void*  ei = d_in[1];
    const float* W0 = (const float*)d_in[2];
    const float* b0 = (const float*)d_in[3];
    const float* W1 = (const float*)d_in[4];
    const float* b1 = (const float*)d_in[5];
    const float* W2 = (const float*)d_in[6];
    const float* b2 = (const float*)d_in[7];
    int E = in_sizes[1] / 2;

    const int SMEM128 = (64 * DIM + DIM * 128) * 4;  // 96 KB
    const int SMEM64  = (64 * DIM + DIM * 64) * 4;   // 64 KB
    cudaFuncSetAttribute(gemm_kernel<128>, cudaFuncAttributeMaxDynamicSharedMemorySize, SMEM128);
    cudaFuncSetAttribute(gemm_kernel<64>,  cudaFuncAttributeMaxDynamicSharedMemorySize, SMEM64);

    int nb_nodes = (N_NODES + 255) / 256;
    int nb_edges = (E + 255) / 256;

    // ---- detect edge dtype, build CSR + normalization ----
    detect_kernel<<<1, 1024>>>((const int*)ei);
    zero_cnt_kernel<<<nb_nodes, 256>>>();
    hist_kernel<<<nb_edges, 256>>>(ei, E);
    dinv_kernel<<<nb_nodes, 256>>>();
    scan_kernel<<<1, 1024>>>(N_NODES);
    scatter_kernel<<<nb_edges, 256>>>(ei, E);
    transpose_kernel<<<(128 * 128 + 255) / 256, 256>>>(W0, 128, 0);
    transpose_kernel<<<(128 * 128 + 255) / 256, 256>>>(W1, 128, 1);
    transpose_kernel<<<(128 * 64 + 255) / 256, 256>>>(W2, 64, 2);

    int gemm_blocks = (N_NODES + 63) / 64;

    // ---- layer 1 ----
    gemm_kernel<128><<<gemm_blocks, 256, SMEM128>>>(x, 0, 0, N_NODES);
    prop_kernel<128, true><<<N_NODES, 128>>>(b0, nullptr, 0);
    // ---- layer 2 ----
    gemm_kernel<128><<<gemm_blocks, 256, SMEM128>>>(nullptr, 1, 1, N_NODES);
    prop_kernel<128, true><<<N_NODES, 128>>>(b1, nullptr, 0);
    // ---- layer 3 (project 128->64 first, then propagate 64-wide) ----
    gemm_kernel<64><<<gemm_blocks, 256, SMEM64>>>(nullptr, 1, 2, N_NODES);
    prop_kernel<64, false><<<N_NODES, 64>>>(b2, (float*)d_out, 1);
}